// round 14
// baseline (speedup 1.0000x reference)
#include <cuda_runtime.h>
#include <cstdint>

// ChamferDistance: B=4, N=8192, C=3 — uniform-grid NN, fused version.
// 2 launches: k_build (8 blocks, one grid each: smem hist -> scan -> scatter)
// and k_query (pruned ring search + fused deterministic sum).
//
// G=16 (h=0.5). Cell scanned only if its box lower bound beats current best;
// boundary-cell boxes extend to infinity outward (clamped outliers sit
// outside their cell box - keeps the bound valid). Ring loop stops when
// best <= (m + R*h)^2, m = distance from q to own cell's nearest face.
// Determinism: min exact under candidate reordering; per-thread best is
// bitwise-stable; block sums use a fixed tree; final sum fixed order.

constexpr int B_    = 4;
constexpr int N_    = 8192;
constexpr int NGRID = 8;                 // gid = b*2 + s (s=0: p1, s=1: p2)
constexpr int G     = 16;
constexpr int CELLS = G * G * G;         // 4096
constexpr float H    = 0.5f;
constexpr float ORG  = -4.0f;
constexpr float INVH = 2.0f;
constexpr int QBLK  = 256;               // query blocks (256 thr each)

__device__ int2   g_rng[NGRID][CELLS];   // {start, count}
__device__ float4 g_pts[NGRID][N_];      // sorted points, .w = original index
__device__ float  g_part[QBLK];
__device__ unsigned int g_done = 0;

__device__ __forceinline__ int cellof(float v) {
    int i = (int)floorf((v - ORG) * INVH);
    return i < 0 ? 0 : (i > G - 1 ? G - 1 : i);
}

// ---- 1. fused build: one block per grid ------------------------------
__global__ __launch_bounds__(1024)
void k_build(const float* __restrict__ p1, const float* __restrict__ p2)
{
    __shared__ int cnt[CELLS];
    __shared__ int cur[CELLS];
    __shared__ int ssum[1024];

    const int gid = blockIdx.x;
    const int tid = threadIdx.x;
    const int b = gid >> 1, s = gid & 1;
    const float* __restrict__ src = (s ? p2 : p1) + (size_t)b * N_ * 3;

    // zero histogram
    #pragma unroll
    for (int k = 0; k < CELLS / 1024; k++) cnt[tid + k * 1024] = 0;
    __syncthreads();

    // histogram: 8 points per thread, coalesced
    #pragma unroll
    for (int k = 0; k < N_ / 1024; k++) {
        const int i = tid + k * 1024;
        const float x = src[i * 3 + 0], y = src[i * 3 + 1], z = src[i * 3 + 2];
        const int c = (cellof(z) * G + cellof(y)) * G + cellof(x);
        atomicAdd(&cnt[c], 1);
    }
    __syncthreads();

    // block scan over 4096 cells (4 per thread)
    const int base = tid * 4;
    int sv = cnt[base] + cnt[base + 1] + cnt[base + 2] + cnt[base + 3];
    ssum[tid] = sv;
    __syncthreads();
    for (int off = 1; off < 1024; off <<= 1) {
        int v = (tid >= off) ? ssum[tid - off] : 0;
        __syncthreads();
        ssum[tid] += v;
        __syncthreads();
    }
    int run = ssum[tid] - sv;     // exclusive prefix for this 4-cell chunk
    #pragma unroll
    for (int j = 0; j < 4; j++) {
        const int c = base + j;
        const int n = cnt[c];
        g_rng[gid][c] = make_int2(run, n);
        cur[c] = run;
        run += n;
    }
    __syncthreads();

    // scatter (re-load points; L2-hot)
    #pragma unroll
    for (int k = 0; k < N_ / 1024; k++) {
        const int i = tid + k * 1024;
        const float x = src[i * 3 + 0], y = src[i * 3 + 1], z = src[i * 3 + 2];
        const int c = (cellof(z) * G + cellof(y)) * G + cellof(x);
        const int pos = atomicAdd(&cur[c], 1);
        g_pts[gid][pos] = make_float4(x, y, z, __int_as_float(i));
    }
}

// scan one cell's point list; unroll 2 for MLP
__device__ __forceinline__ float scan_cell(const float4* __restrict__ pts,
                                           int2 rg, float qx, float qy, float qz,
                                           float best)
{
    int t = rg.x;
    const int e = rg.x + rg.y;
    float b0 = best, b1 = 1e30f;
    for (; t + 1 < e; t += 2) {
        const float4 A = pts[t];
        const float4 Bp = pts[t + 1];
        const float ax = qx - A.x, ay = qy - A.y, az = qz - A.z;
        const float bx = qx - Bp.x, by = qy - Bp.y, bz = qz - Bp.z;
        float d0 = ax * ax; d0 = fmaf(ay, ay, d0); d0 = fmaf(az, az, d0);
        float d1 = bx * bx; d1 = fmaf(by, by, d1); d1 = fmaf(bz, bz, d1);
        b0 = fminf(b0, d0);
        b1 = fminf(b1, d1);
    }
    if (t < e) {
        const float4 A = pts[t];
        const float ax = qx - A.x, ay = qy - A.y, az = qz - A.z;
        float d0 = ax * ax; d0 = fmaf(ay, ay, d0); d0 = fmaf(az, az, d0);
        b0 = fminf(b0, d0);
    }
    return fminf(b0, b1);
}

// per-axis box distance with boundary cells extended to infinity outward
__device__ __forceinline__ float axdist(int c, float qv) {
    const float lo = ORG + c * H;
    const float dlo = (c == 0)     ? 0.0f : lo - qv;       // -inf face at c==0
    const float dhi = (c == G - 1) ? 0.0f : qv - lo - H;   // +inf face at c==G-1
    return fmaxf(fmaxf(dlo, dhi), 0.0f);
}

// ---- 2. pruned ring-search query + fused deterministic sum -----------
__global__ __launch_bounds__(256)
void k_query(float* __restrict__ out)
{
    const int idx = blockIdx.x * 256 + threadIdx.x;   // 65536
    const int gid = idx >> 13, i = idx & (N_ - 1);
    const int og  = gid ^ 1;
    const int tid = threadIdx.x;

    const float4 qp = g_pts[gid][i];                  // sorted -> coherent warps
    const float qx = qp.x, qy = qp.y, qz = qp.z;
    const int cx = cellof(qx), cy = cellof(qy), cz = cellof(qz);

    // margin to own cell's nearest face (conservative: clamped -> 0)
    const float lox = ORG + cx * H, loy = ORG + cy * H, loz = ORG + cz * H;
    float m = fminf(fminf(qx - lox, lox + H - qx),
             fminf(fminf(qy - loy, loy + H - qy),
                   fminf(qz - loz, loz + H - qz)));
    m = fmaxf(m, 0.0f);

    const int2*   __restrict__ rng = g_rng[og];
    const float4* __restrict__ pts = g_pts[og];

    float best = 1e30f;
    for (int R = 0; R < G; R++) {
        if (R == 0) {
            best = scan_cell(pts, rng[(cz * G + cy) * G + cx], qx, qy, qz, best);
        } else {
            for (int dz = -R; dz <= R; dz++) {
                const int z = cz + dz;
                if ((unsigned)z >= (unsigned)G) continue;
                const float dzb = axdist(z, qz);
                const float dz2 = dzb * dzb;
                if (dz2 >= best) continue;
                const bool zedge = (dz == -R) | (dz == R);
                for (int dy = -R; dy <= R; dy++) {
                    const int y = cy + dy;
                    if ((unsigned)y >= (unsigned)G) continue;
                    const float dyb = axdist(y, qy);
                    const float dzy2 = fmaf(dyb, dyb, dz2);
                    if (dzy2 >= best) continue;
                    const bool edge = zedge | (dy == -R) | (dy == R);
                    const int step = edge ? 1 : 2 * R;
                    for (int dx = -R; dx <= R; dx += step) {
                        const int x = cx + dx;
                        if ((unsigned)x >= (unsigned)G) continue;
                        const float dxb = axdist(x, qx);
                        const float lb2 = fmaf(dxb, dxb, dzy2);
                        if (lb2 >= best) continue;      // box-prune
                        const int2 rg = rng[(z * G + y) * G + x];
                        if (rg.y == 0) continue;
                        best = scan_cell(pts, rg, qx, qy, qz, best);
                    }
                }
            }
        }
        const float bound = m + (float)R * H;   // unvisited cells >= this far
        if (best <= bound * bound) break;
    }

    // ---- fused deterministic reduction ----
    float sv = best;
    #pragma unroll
    for (int o = 16; o > 0; o >>= 1)
        sv += __shfl_down_sync(0xffffffffu, sv, o);
    __shared__ float red[8];
    __shared__ bool  amLast;
    if ((tid & 31) == 0) red[tid >> 5] = sv;
    __syncthreads();
    if (tid == 0) {
        float bs = 0.0f;
        #pragma unroll
        for (int wi = 0; wi < 8; wi++) bs += red[wi];
        g_part[blockIdx.x] = bs;
        __threadfence();
        amLast = (atomicAdd(&g_done, 1u) == QBLK - 1);
    }
    __syncthreads();

    if (amLast) {
        float v = g_part[tid];            // 256 threads, 256 partials
        #pragma unroll
        for (int o = 16; o > 0; o >>= 1)
            v += __shfl_down_sync(0xffffffffu, v, o);
        if ((tid & 31) == 0) red[tid >> 5] = v;
        __syncthreads();
        if (tid == 0) {
            float t = 0.0f;
            #pragma unroll
            for (int wi = 0; wi < 8; wi++) t += red[wi];
            out[0] = t * (1.0f / (float)N_);
            g_done = 0;                   // reset for next graph replay
        }
    }
}

extern "C" void kernel_launch(void* const* d_in, const int* in_sizes, int n_in,
                              void* d_out, int out_size)
{
    const float* points1 = (const float*)d_in[0];
    const float* points2 = (const float*)d_in[1];
    float* out = (float*)d_out;

    k_build<<<NGRID, 1024>>>(points1, points2);
    k_query<<<QBLK, 256>>>(out);
}